// round 3
// baseline (speedup 1.0000x reference)
#include <cuda_runtime.h>
#include <math.h>

// Problem constants
#define BB 16
#define HH 16
#define NN 577
#define DD 64
#define CC 1024
#define MTOK (BB*NN)            // 9232
#define PLANE (BB*HH*NN*DD)     // 9,453,568 floats per q/k/v plane
#define OUT_ELEMS (MTOK*CC)     // 9,453,568
#define CTA_OFS OUT_ELEMS
#define CTL_OFS (OUT_ELEMS + MTOK)
#define QSCALE 0.125f           // 1/sqrt(64)

typedef unsigned long long u64;

// Packed fp32 ops (Blackwell f32x2 pipe — 2 FMAs per fma-pipe slot)
#define FMA2(c,a,b)  asm("fma.rn.f32x2 %0, %1, %2, %0;" : "+l"(c) : "l"(a), "l"(b))
#define MUL2(d,a,b)  asm("mul.rn.f32x2 %0, %1, %2;" : "=l"(d) : "l"(a), "l"(b))
#define DUP2(d,s)    asm("mov.b64 %0, {%1, %1};" : "=l"(d) : "r"(s))

__device__ __forceinline__ u64 dup_f32(float v) {
    u64 r; unsigned int u = __float_as_uint(v); DUP2(r, u); return r;
}
__device__ __forceinline__ float lo_f32(u64 p) { return __uint_as_float((unsigned int)p); }
__device__ __forceinline__ float hi_f32(u64 p) { return __uint_as_float((unsigned int)(p >> 32)); }

// Scratch (device globals: allocation-free per harness rules)
__device__ float g_qkv[3u * PLANE];       // [3][B][H][N][D], q pre-scaled
__device__ float g_attn[OUT_ELEMS];       // [B][N][C] attention output
__device__ float g_cls_logits[BB*HH*NN];  // per-head CLS-row logits
__device__ float g_cls_max[BB*HH];
__device__ float g_cls_den[BB*HH];

// ---------------------------------------------------------------------------
// Tiled fp32 GEMM with packed f32x2 FMAs: C[m,n] = sum_k A[m,k]*W[n,k] (+bias)
// A row-major [M,K], W row-major [N,K].
// A is stored DUPLICATED in smem (each value twice) so the a-operand of
// fma.rn.f32x2 can be loaded pre-broadcast with a single LDS.64.
// mode 1: QKV epilogue -> scatter into g_qkv (q scaled)
// mode 2: A taken from g_attn, plain epilogue into Cout
// BM=BN=128, BK=8, 256 threads, 8x8 per-thread microtile (as 8x4 f32x2 pairs)
// ---------------------------------------------------------------------------
__global__ __launch_bounds__(256) void sgemm_nt(
    const float* __restrict__ A, const float* __restrict__ W,
    const float* __restrict__ bias, float* __restrict__ Cout,
    int M, int N, int K, int mode)
{
    __shared__ float As[8][264];   // duplicated: As[k][2*row+{0,1}] = a[row]
    __shared__ float Ws[8][132];

    const float* Abase = (mode == 2) ? g_attn : A;

    const int tid = threadIdx.x;
    const int bm  = blockIdx.y * 128;
    const int bn  = blockIdx.x * 128;
    const int lr  = tid >> 1;          // 0..127 tile row for loads
    const int lc  = (tid & 1) << 2;    // 0 or 4 (float4 column)
    const int tx  = tid & 15;
    const int ty  = tid >> 4;

    const int arow = (bm + lr < M) ? (bm + lr) : (M - 1);
    const bool avalid = (bm + lr) < M;
    const float* Ap = Abase + (size_t)arow * K + lc;
    const float* Wp = W + (size_t)(bn + lr) * K + lc;

    u64 acc2[8][4];
    #pragma unroll
    for (int i = 0; i < 8; i++)
        #pragma unroll
        for (int j = 0; j < 4; j++) acc2[i][j] = 0ull;

    for (int k0 = 0; k0 < K; k0 += 8) {
        float4 av = avalid ? *(const float4*)(Ap + k0) : make_float4(0.f,0.f,0.f,0.f);
        float4 wv = *(const float4*)(Wp + k0);
        __syncthreads();
        *(float2*)&As[lc+0][2*lr] = make_float2(av.x, av.x);
        *(float2*)&As[lc+1][2*lr] = make_float2(av.y, av.y);
        *(float2*)&As[lc+2][2*lr] = make_float2(av.z, av.z);
        *(float2*)&As[lc+3][2*lr] = make_float2(av.w, av.w);
        Ws[lc+0][lr] = wv.x; Ws[lc+1][lr] = wv.y; Ws[lc+2][lr] = wv.z; Ws[lc+3][lr] = wv.w;
        __syncthreads();
        #pragma unroll
        for (int kk = 0; kk < 8; kk++) {
            u64 a2[8], b2[4];
            const u64* apd = (const u64*)&As[kk][ty*16];
            #pragma unroll
            for (int i = 0; i < 8; i++) a2[i] = apd[i];
            const u64* bpd = (const u64*)&Ws[kk][tx*8];
            #pragma unroll
            for (int j = 0; j < 4; j++) b2[j] = bpd[j];
            #pragma unroll
            for (int i = 0; i < 8; i++)
                #pragma unroll
                for (int j = 0; j < 4; j++)
                    FMA2(acc2[i][j], a2[i], b2[j]);
        }
    }

    if (mode == 1) {
        // QKV scatter: n -> (which, h, d); m -> (b, tok)
        #pragma unroll
        for (int i = 0; i < 8; i++) {
            int m = bm + ty*8 + i;
            if (m >= M) continue;
            int b_ = m / NN;
            int tok = m - b_ * NN;
            #pragma unroll
            for (int j2 = 0; j2 < 4; j2++) {
                float cv[2] = { lo_f32(acc2[i][j2]), hi_f32(acc2[i][j2]) };
                #pragma unroll
                for (int e = 0; e < 2; e++) {
                    int n = bn + tx*8 + j2*2 + e;
                    float v = cv[e] + bias[n];
                    int which = n >> 10;          // /1024
                    int rest  = n & 1023;
                    int h = rest >> 6;
                    int d = rest & 63;
                    if (which == 0) v *= QSCALE;
                    g_qkv[(size_t)which * PLANE + (((size_t)(b_*HH + h) * NN + tok) << 6) + d] = v;
                }
            }
        }
    } else {
        #pragma unroll
        for (int i = 0; i < 8; i++) {
            int m = bm + ty*8 + i;
            if (m >= M) continue;
            #pragma unroll
            for (int j2 = 0; j2 < 4; j2++) {
                int n = bn + tx*8 + j2*2;
                Cout[(size_t)m * N + n]     = lo_f32(acc2[i][j2]) + bias[n];
                Cout[(size_t)m * N + n + 1] = hi_f32(acc2[i][j2]) + bias[n+1];
            }
        }
    }
}

// ---------------------------------------------------------------------------
// Flash attention with packed f32x2 FMAs: grid (10 q-tiles, 256 bh), 256 thr.
// BQ=64, key tiles of 64. Thread t: query row r=t/4, key lane l4=t%4.
// S packs along the reduction dim d (horizontal add at end of dot product).
// PV packs along output dims (p duplicated via mov.b64).
// ---------------------------------------------------------------------------
#define SROW 68
#define FLASH_SMEM (4 * 64 * SROW * 4)

__global__ __launch_bounds__(256) void flash_attn_kernel()
{
    extern __shared__ float sm[];
    float* Qs = sm;
    float* Ks = sm + 64*SROW;
    float* Vs = sm + 2*64*SROW;
    float* Ps = sm + 3*64*SROW;

    const int tid = threadIdx.x;
    const int qt  = blockIdx.x;     // 0..9
    const int bh  = blockIdx.y;     // 0..255
    const int q0g = qt * 64;

    const float* Qg = g_qkv + (size_t)bh * NN * DD;
    const float* Kg = g_qkv + (size_t)PLANE + (size_t)bh * NN * DD;
    const float* Vg = g_qkv + 2u*(size_t)PLANE + (size_t)bh * NN * DD;

    // load Q tile (zero-pad invalid rows)
    #pragma unroll
    for (int i = 0; i < 4; i++) {
        int p = i*256 + tid;       // float4 index, 1024 total
        int row = p >> 4;
        int c4  = (p & 15) << 2;
        float4 v = (q0g + row < NN) ? *(const float4*)(Qg + (size_t)(q0g+row)*DD + c4)
                                    : make_float4(0.f,0.f,0.f,0.f);
        *(float4*)(Qs + row*SROW + c4) = v;
    }

    const int r  = tid >> 2;       // query row in tile
    const int l4 = tid & 3;
    const int d0 = l4 * 16;

    u64 acc2[8];                    // 16 output dims as 8 f32x2 pairs
    #pragma unroll
    for (int i = 0; i < 8; i++) acc2[i] = 0ull;
    float m_i = -1e30f, l_i = 0.f;

    for (int kt = 0; kt < 10; kt++) {
        const int k0g = kt * 64;
        __syncthreads();  // previous tile's Ps/Vs consumption done (also covers Q tile)
        #pragma unroll
        for (int i = 0; i < 4; i++) {
            int p = i*256 + tid;
            int row = p >> 4;
            int c4  = (p & 15) << 2;
            bool ok = (k0g + row) < NN;
            float4 kv = ok ? *(const float4*)(Kg + (size_t)(k0g+row)*DD + c4) : make_float4(0.f,0.f,0.f,0.f);
            float4 vv = ok ? *(const float4*)(Vg + (size_t)(k0g+row)*DD + c4) : make_float4(0.f,0.f,0.f,0.f);
            *(float4*)(Ks + row*SROW + c4) = kv;
            *(float4*)(Vs + row*SROW + c4) = vv;
        }
        __syncthreads();

        // S: 16 keys per thread (j = l4 + 4*jj); pack along d
        u64 s2[16];
        #pragma unroll
        for (int jj = 0; jj < 16; jj++) s2[jj] = 0ull;
        #pragma unroll
        for (int d4 = 0; d4 < 64; d4 += 4) {
            float4 q4 = *(const float4*)(Qs + r*SROW + d4);
            const u64* qp = (const u64*)&q4;
            u64 qa = qp[0], qb = qp[1];
            #pragma unroll
            for (int jj = 0; jj < 16; jj++) {
                int j = l4 + (jj << 2);
                float4 k4 = *(const float4*)(Ks + j*SROW + d4);
                const u64* kp = (const u64*)&k4;
                FMA2(s2[jj], qa, kp[0]);
                FMA2(s2[jj], qb, kp[1]);
            }
        }
        float s[16];
        #pragma unroll
        for (int jj = 0; jj < 16; jj++) s[jj] = lo_f32(s2[jj]) + hi_f32(s2[jj]);

        // mask + row max (reduce over 4 lanes of this row)
        float mloc = -1e30f;
        #pragma unroll
        for (int jj = 0; jj < 16; jj++) {
            int jg = k0g + l4 + (jj << 2);
            if (jg >= NN) s[jj] = -1e30f;
            mloc = fmaxf(mloc, s[jj]);
        }
        mloc = fmaxf(mloc, __shfl_xor_sync(0xffffffffu, mloc, 1));
        mloc = fmaxf(mloc, __shfl_xor_sync(0xffffffffu, mloc, 2));
        float m_new = fmaxf(m_i, mloc);
        float alpha = __expf(m_i - m_new);

        float psum = 0.f;
        #pragma unroll
        for (int jj = 0; jj < 16; jj++) {
            float pv = (s[jj] > -1e29f) ? __expf(s[jj] - m_new) : 0.f;
            psum += pv;
            Ps[r*SROW + l4 + (jj << 2)] = pv;
        }
        psum += __shfl_xor_sync(0xffffffffu, psum, 1);
        psum += __shfl_xor_sync(0xffffffffu, psum, 2);
        l_i = l_i * alpha + psum;
        m_i = m_new;
        {
            u64 alpha2 = dup_f32(alpha);
            #pragma unroll
            for (int i = 0; i < 8; i++) MUL2(acc2[i], acc2[i], alpha2);
        }
        __syncthreads();  // Ps visible

        // O += P @ V (thread's 16 dims as 8 pairs, all 64 keys)
        #pragma unroll
        for (int j = 0; j < 64; j++) {
            u64 p2 = dup_f32(Ps[r*SROW + j]);
            const float* vrow = Vs + j*SROW + d0;
            float4 v0 = *(const float4*)(vrow);
            float4 v1 = *(const float4*)(vrow + 4);
            float4 v2 = *(const float4*)(vrow + 8);
            float4 v3 = *(const float4*)(vrow + 12);
            const u64* vp0 = (const u64*)&v0;
            const u64* vp1 = (const u64*)&v1;
            const u64* vp2 = (const u64*)&v2;
            const u64* vp3 = (const u64*)&v3;
            FMA2(acc2[0], p2, vp0[0]); FMA2(acc2[1], p2, vp0[1]);
            FMA2(acc2[2], p2, vp1[0]); FMA2(acc2[3], p2, vp1[1]);
            FMA2(acc2[4], p2, vp2[0]); FMA2(acc2[5], p2, vp2[1]);
            FMA2(acc2[6], p2, vp3[0]); FMA2(acc2[7], p2, vp3[1]);
        }
    }

    const int qg = q0g + r;
    if (qg < NN) {
        float inv = 1.f / l_i;
        int b_ = bh >> 4, h = bh & 15;
        float* o = g_attn + ((size_t)b_ * NN + qg) * CC + h * DD + d0;
        #pragma unroll
        for (int i = 0; i < 8; i += 2) {
            float4 v = make_float4(lo_f32(acc2[i])*inv,   hi_f32(acc2[i])*inv,
                                   lo_f32(acc2[i+1])*inv, hi_f32(acc2[i+1])*inv);
            *(float4*)(o + i*2) = v;
        }
    }
}

// ---------------------------------------------------------------------------
// CLS-row logits per (b,h): logits[m] = q0 . k[m]; also max & softmax denom
// ---------------------------------------------------------------------------
__global__ __launch_bounds__(128) void cls_logits_kernel()
{
    __shared__ float q0s[64];
    __shared__ float red[128];
    const int bh  = blockIdx.x;
    const int tid = threadIdx.x;
    const float* Qg = g_qkv + (size_t)bh * NN * DD;            // q already scaled
    const float* Kg = g_qkv + (size_t)PLANE + (size_t)bh * NN * DD;

    if (tid < 64) q0s[tid] = Qg[tid];
    __syncthreads();

    float lg[5];
    float mloc = -1e30f;
    #pragma unroll
    for (int i = 0; i < 5; i++) {
        int m = tid + i*128;
        float s = -1e30f;
        if (m < NN) {
            s = 0.f;
            const float* kr = Kg + (size_t)m * DD;
            #pragma unroll
            for (int d4 = 0; d4 < 64; d4 += 4) {
                float4 k4 = *(const float4*)(kr + d4);
                s += q0s[d4]*k4.x + q0s[d4+1]*k4.y + q0s[d4+2]*k4.z + q0s[d4+3]*k4.w;
            }
            g_cls_logits[(size_t)bh * NN + m] = s;
        }
        lg[i] = s;
        mloc = fmaxf(mloc, s);
    }

    red[tid] = mloc; __syncthreads();
    for (int o = 64; o > 0; o >>= 1) {
        if (tid < o) red[tid] = fmaxf(red[tid], red[tid+o]);
        __syncthreads();
    }
    float mx = red[0];
    __syncthreads();

    float se = 0.f;
    #pragma unroll
    for (int i = 0; i < 5; i++)
        if (lg[i] > -1e29f) se += __expf(lg[i] - mx);
    red[tid] = se; __syncthreads();
    for (int o = 64; o > 0; o >>= 1) {
        if (tid < o) red[tid] += red[tid+o];
        __syncthreads();
    }
    if (tid == 0) { g_cls_max[bh] = mx; g_cls_den[bh] = red[0]; }
}

// Head-mean of CLS logits and CLS attention
__global__ void cls_out_kernel(float* __restrict__ out_cta, float* __restrict__ out_ctl)
{
    int idx = blockIdx.x * blockDim.x + threadIdx.x;
    if (idx >= MTOK) return;
    int b_ = idx / NN;
    int m  = idx - b_ * NN;
    float sl = 0.f, sa = 0.f;
    #pragma unroll
    for (int h = 0; h < HH; h++) {
        int bh = b_ * HH + h;
        float l = g_cls_logits[(size_t)bh * NN + m];
        sl += l;
        sa += __expf(l - g_cls_max[bh]) / g_cls_den[bh];
    }
    out_ctl[idx] = sl * (1.f / 16.f);
    out_cta[idx] = sa * (1.f / 16.f);
}

// ---------------------------------------------------------------------------
extern "C" void kernel_launch(void* const* d_in, const int* in_sizes, int n_in,
                              void* d_out, int out_size)
{
    const float* x      = (const float*)d_in[0];
    const float* w_qkv  = (const float*)d_in[1];
    const float* b_qkv  = (const float*)d_in[2];
    const float* w_proj = (const float*)d_in[3];
    const float* b_proj = (const float*)d_in[4];
    float* out = (float*)d_out;

    // 1) QKV projection + scatter (q scaled)
    {
        dim3 grid(3*CC/128, (MTOK + 127) / 128);
        sgemm_nt<<<grid, 256>>>(x, w_qkv, b_qkv, nullptr, MTOK, 3*CC, CC, 1);
    }

    // 2) Flash attention
    cudaFuncSetAttribute(flash_attn_kernel,
                         cudaFuncAttributeMaxDynamicSharedMemorySize, FLASH_SMEM);
    {
        dim3 grid(10, BB*HH);
        flash_attn_kernel<<<grid, 256, FLASH_SMEM>>>();
    }

    // 3) CLS-row outputs
    cls_logits_kernel<<<BB*HH, 128>>>();
    cls_out_kernel<<<(MTOK + 255) / 256, 256>>>(out + CTA_OFS, out + CTL_OFS);

    // 4) Output projection
    {
        dim3 grid(CC/128, (MTOK + 127) / 128);
        sgemm_nt<<<grid, 256>>>(nullptr, w_proj, b_proj, out, MTOK, CC, CC, 2);
    }
}

// round 4
// speedup vs baseline: 1.5583x; 1.5583x over previous
#include <cuda_runtime.h>
#include <math.h>

// Problem constants
#define BB 16
#define HH 16
#define NN 577
#define DD 64
#define CC 1024
#define MTOK (BB*NN)            // 9232
#define PLANE (BB*HH*NN*DD)     // 9,453,568 floats per q/k/v plane
#define OUT_ELEMS (MTOK*CC)     // 9,453,568
#define CTA_OFS OUT_ELEMS
#define CTL_OFS (OUT_ELEMS + MTOK)
#define QSCALE 0.125f           // 1/sqrt(64)

// Scratch (device globals: allocation-free per harness rules)
__device__ float g_qkv[3u * PLANE];       // [3][B][H][N][D], q pre-scaled
__device__ float g_attn[OUT_ELEMS];       // [B][N][C] attention output
__device__ float g_cls_logits[BB*HH*NN];  // per-head CLS-row logits
__device__ float g_cls_max[BB*HH];
__device__ float g_cls_den[BB*HH];

__device__ __forceinline__ unsigned int f2tf32(float f) {
    unsigned int r;
    asm("cvt.rna.tf32.f32 %0, %1;" : "=r"(r) : "f"(f));
    return r;
}

#define MMA_TF32(d, a, b) \
    asm("mma.sync.aligned.m16n8k8.row.col.f32.tf32.tf32.f32 " \
        "{%0,%1,%2,%3}, {%4,%5,%6,%7}, {%8,%9}, {%0,%1,%2,%3};" \
        : "+f"((d)[0]), "+f"((d)[1]), "+f"((d)[2]), "+f"((d)[3]) \
        : "r"((a)[0]), "r"((a)[1]), "r"((a)[2]), "r"((a)[3]), \
          "r"((b)[0]), "r"((b)[1]))

// ---------------------------------------------------------------------------
// tf32 tensor-core GEMM: C[m,n] = sum_k A[m,k] * W[n,k] (+bias). K = 1024.
// A row-major [M,K], W row-major [N,K] (k-contiguous = mma "col" B operand).
// BM=BN=128, BK=32, 256 threads (8 warps as 4m x 2n, warp tile 32x64).
// mode 1: QKV epilogue -> scatter into g_qkv (q scaled)
// mode 2: A taken from g_attn, plain epilogue into Cout
// ---------------------------------------------------------------------------
#define GSTRIDE 36   // smem row stride in words: bank = row*4+col -> conflict-free

__global__ __launch_bounds__(256) void mma_gemm_nt(
    const float* __restrict__ A, const float* __restrict__ W,
    const float* __restrict__ bias, float* __restrict__ Cout,
    int M, int N, int mode)
{
    __shared__ unsigned int As[128 * GSTRIDE];
    __shared__ unsigned int Ws[128 * GSTRIDE];
    const int K = 1024;

    const float* Abase = (mode == 2) ? g_attn : A;

    const int tid  = threadIdx.x;
    const int lane = tid & 31;
    const int warp = tid >> 5;
    const int wm   = warp & 3;     // warp row (m): 0..3 -> 32 rows each
    const int wn   = warp >> 2;    // warp col (n): 0..1 -> 64 cols each
    const int bm   = blockIdx.y * 128;
    const int bn   = blockIdx.x * 128;

    float acc[2][8][4];
    #pragma unroll
    for (int i = 0; i < 2; i++)
        #pragma unroll
        for (int j = 0; j < 8; j++)
            #pragma unroll
            for (int e = 0; e < 4; e++) acc[i][j][e] = 0.f;

    const int g  = lane >> 2;      // group id 0..7
    const int tg = lane & 3;       // thread in group 0..3

    for (int k0 = 0; k0 < K; k0 += 32) {
        // global loads: 128 rows x 8 float4 = 1024 float4, 4 per thread
        float4 av[4], wv[4];
        #pragma unroll
        for (int i = 0; i < 4; i++) {
            int p   = i * 256 + tid;
            int row = p >> 3;
            int c4  = (p & 7) << 2;
            int ar  = bm + row;
            const float* ap = Abase + (size_t)((ar < M) ? ar : (M - 1)) * K + k0 + c4;
            av[i] = (ar < M) ? *(const float4*)ap : make_float4(0.f, 0.f, 0.f, 0.f);
            wv[i] = *(const float4*)(W + (size_t)(bn + row) * K + k0 + c4);
        }
        __syncthreads();
        #pragma unroll
        for (int i = 0; i < 4; i++) {
            int p   = i * 256 + tid;
            int row = p >> 3;
            int c4  = (p & 7) << 2;
            uint4 at = make_uint4(f2tf32(av[i].x), f2tf32(av[i].y), f2tf32(av[i].z), f2tf32(av[i].w));
            uint4 wt = make_uint4(f2tf32(wv[i].x), f2tf32(wv[i].y), f2tf32(wv[i].z), f2tf32(wv[i].w));
            *(uint4*)(As + row * GSTRIDE + c4) = at;
            *(uint4*)(Ws + row * GSTRIDE + c4) = wt;
        }
        __syncthreads();

        #pragma unroll
        for (int ks = 0; ks < 4; ks++) {
            const int kb = ks << 3;
            unsigned int af[2][4], bf[8][2];
            #pragma unroll
            for (int mt = 0; mt < 2; mt++) {
                int r0 = wm * 32 + mt * 16 + g;
                af[mt][0] = As[r0 * GSTRIDE + kb + tg];
                af[mt][1] = As[(r0 + 8) * GSTRIDE + kb + tg];
                af[mt][2] = As[r0 * GSTRIDE + kb + tg + 4];
                af[mt][3] = As[(r0 + 8) * GSTRIDE + kb + tg + 4];
            }
            #pragma unroll
            for (int nt = 0; nt < 8; nt++) {
                int nr = wn * 64 + nt * 8 + g;
                bf[nt][0] = Ws[nr * GSTRIDE + kb + tg];
                bf[nt][1] = Ws[nr * GSTRIDE + kb + tg + 4];
            }
            #pragma unroll
            for (int mt = 0; mt < 2; mt++)
                #pragma unroll
                for (int nt = 0; nt < 8; nt++)
                    MMA_TF32(acc[mt][nt], af[mt], bf[nt]);
        }
    }

    // Epilogue. c-elem e: row += (e>=2)*8, col = tg*2 + (e&1)
    #pragma unroll
    for (int mt = 0; mt < 2; mt++) {
        #pragma unroll
        for (int eh = 0; eh < 2; eh++) {          // half: rows g / g+8
            int m = bm + wm * 32 + mt * 16 + g + eh * 8;
            if (m >= M) continue;
            if (mode == 1) {
                int b_  = m / NN;
                int tok = m - b_ * NN;
                #pragma unroll
                for (int nt = 0; nt < 8; nt++) {
                    #pragma unroll
                    for (int ec = 0; ec < 2; ec++) {
                        int n = bn + wn * 64 + nt * 8 + tg * 2 + ec;
                        float v = acc[mt][nt][eh * 2 + ec] + bias[n];
                        int which = n >> 10;
                        int rest  = n & 1023;
                        int h = rest >> 6;
                        int d = rest & 63;
                        if (which == 0) v *= QSCALE;
                        g_qkv[(size_t)which * PLANE + (((size_t)(b_ * HH + h) * NN + tok) << 6) + d] = v;
                    }
                }
            } else {
                #pragma unroll
                for (int nt = 0; nt < 8; nt++) {
                    int n = bn + wn * 64 + nt * 8 + tg * 2;
                    float2 v = make_float2(acc[mt][nt][eh * 2 + 0] + bias[n],
                                           acc[mt][nt][eh * 2 + 1] + bias[n + 1]);
                    *(float2*)(Cout + (size_t)m * N + n) = v;
                }
            }
        }
    }
}

// ---------------------------------------------------------------------------
// Flash attention: grid (q_tiles=10, BH=256), 256 threads.
// BQ=64 queries, key tiles of 64. Thread t: query row r=t/4, dims d0=(t%4)*16.
// smem rows padded to 68 floats (bank-conflict-free, float4-aligned).
// ---------------------------------------------------------------------------
#define SROW 68
#define FLASH_SMEM (4 * 64 * SROW * 4)

__global__ __launch_bounds__(256) void flash_attn_kernel()
{
    extern __shared__ float sm[];
    float* Qs = sm;
    float* Ks = sm + 64*SROW;
    float* Vs = sm + 2*64*SROW;
    float* Ps = sm + 3*64*SROW;

    const int tid = threadIdx.x;
    const int qt  = blockIdx.x;     // 0..9
    const int bh  = blockIdx.y;     // 0..255
    const int q0g = qt * 64;

    const float* Qg = g_qkv + (size_t)bh * NN * DD;
    const float* Kg = g_qkv + (size_t)PLANE + (size_t)bh * NN * DD;
    const float* Vg = g_qkv + 2u*(size_t)PLANE + (size_t)bh * NN * DD;

    // load Q tile (zero-pad invalid rows)
    #pragma unroll
    for (int i = 0; i < 4; i++) {
        int p = i*256 + tid;       // float4 index, 1024 total
        int row = p >> 4;
        int c4  = (p & 15) << 2;
        float4 v = (q0g + row < NN) ? *(const float4*)(Qg + (size_t)(q0g+row)*DD + c4)
                                    : make_float4(0.f,0.f,0.f,0.f);
        *(float4*)(Qs + row*SROW + c4) = v;
    }

    const int r  = tid >> 2;       // query row in tile
    const int l4 = tid & 3;
    const int d0 = l4 * 16;

    float acc[16];
    #pragma unroll
    for (int i = 0; i < 16; i++) acc[i] = 0.f;
    float m_i = -1e30f, l_i = 0.f;

    for (int kt = 0; kt < 10; kt++) {
        const int k0g = kt * 64;
        __syncthreads();  // previous tile's Ps/Vs consumption done (also covers Q tile)
        #pragma unroll
        for (int i = 0; i < 4; i++) {
            int p = i*256 + tid;
            int row = p >> 4;
            int c4  = (p & 15) << 2;
            bool ok = (k0g + row) < NN;
            float4 kv = ok ? *(const float4*)(Kg + (size_t)(k0g+row)*DD + c4) : make_float4(0.f,0.f,0.f,0.f);
            float4 vv = ok ? *(const float4*)(Vg + (size_t)(k0g+row)*DD + c4) : make_float4(0.f,0.f,0.f,0.f);
            *(float4*)(Ks + row*SROW + c4) = kv;
            *(float4*)(Vs + row*SROW + c4) = vv;
        }
        __syncthreads();

        // S: 16 keys per thread (j = l4 + 4*jj)
        float s[16];
        #pragma unroll
        for (int jj = 0; jj < 16; jj++) s[jj] = 0.f;
        #pragma unroll
        for (int d4 = 0; d4 < 64; d4 += 4) {
            float4 q4 = *(const float4*)(Qs + r*SROW + d4);
            #pragma unroll
            for (int jj = 0; jj < 16; jj++) {
                int j = l4 + (jj << 2);
                float4 k4 = *(const float4*)(Ks + j*SROW + d4);
                s[jj] += q4.x*k4.x + q4.y*k4.y + q4.z*k4.z + q4.w*k4.w;
            }
        }

        // mask + row max (reduce over 4 lanes of this row)
        float mloc = -1e30f;
        #pragma unroll
        for (int jj = 0; jj < 16; jj++) {
            int jg = k0g + l4 + (jj << 2);
            if (jg >= NN) s[jj] = -1e30f;
            mloc = fmaxf(mloc, s[jj]);
        }
        mloc = fmaxf(mloc, __shfl_xor_sync(0xffffffffu, mloc, 1));
        mloc = fmaxf(mloc, __shfl_xor_sync(0xffffffffu, mloc, 2));
        float m_new = fmaxf(m_i, mloc);
        float alpha = __expf(m_i - m_new);

        float psum = 0.f;
        #pragma unroll
        for (int jj = 0; jj < 16; jj++) {
            float pv = (s[jj] > -1e29f) ? __expf(s[jj] - m_new) : 0.f;
            psum += pv;
            Ps[r*SROW + l4 + (jj << 2)] = pv;
        }
        psum += __shfl_xor_sync(0xffffffffu, psum, 1);
        psum += __shfl_xor_sync(0xffffffffu, psum, 2);
        l_i = l_i * alpha + psum;
        m_i = m_new;
        #pragma unroll
        for (int i = 0; i < 16; i++) acc[i] *= alpha;
        __syncthreads();  // Ps visible

        // O += P @ V (thread's 16 dims, all 64 keys)
        #pragma unroll
        for (int j = 0; j < 64; j++) {
            float pv = Ps[r*SROW + j];
            const float* vrow = Vs + j*SROW + d0;
            float4 v0 = *(const float4*)(vrow);
            float4 v1 = *(const float4*)(vrow + 4);
            float4 v2 = *(const float4*)(vrow + 8);
            float4 v3 = *(const float4*)(vrow + 12);
            acc[0]  += pv*v0.x; acc[1]  += pv*v0.y; acc[2]  += pv*v0.z; acc[3]  += pv*v0.w;
            acc[4]  += pv*v1.x; acc[5]  += pv*v1.y; acc[6]  += pv*v1.z; acc[7]  += pv*v1.w;
            acc[8]  += pv*v2.x; acc[9]  += pv*v2.y; acc[10] += pv*v2.z; acc[11] += pv*v2.w;
            acc[12] += pv*v3.x; acc[13] += pv*v3.y; acc[14] += pv*v3.z; acc[15] += pv*v3.w;
        }
    }

    const int qg = q0g + r;
    if (qg < NN) {
        float inv = 1.f / l_i;
        int b_ = bh >> 4, h = bh & 15;
        float* o = g_attn + ((size_t)b_ * NN + qg) * CC + h * DD + d0;
        #pragma unroll
        for (int i = 0; i < 16; i += 4) {
            float4 v = make_float4(acc[i]*inv, acc[i+1]*inv, acc[i+2]*inv, acc[i+3]*inv);
            *(float4*)(o + i) = v;
        }
    }
}

// ---------------------------------------------------------------------------
// CLS-row logits per (b,h): logits[m] = q0 . k[m]; also max & softmax denom
// ---------------------------------------------------------------------------
__global__ __launch_bounds__(128) void cls_logits_kernel()
{
    __shared__ float q0s[64];
    __shared__ float red[128];
    const int bh  = blockIdx.x;
    const int tid = threadIdx.x;
    const float* Qg = g_qkv + (size_t)bh * NN * DD;            // q already scaled
    const float* Kg = g_qkv + (size_t)PLANE + (size_t)bh * NN * DD;

    if (tid < 64) q0s[tid] = Qg[tid];
    __syncthreads();

    float lg[5];
    float mloc = -1e30f;
    #pragma unroll
    for (int i = 0; i < 5; i++) {
        int m = tid + i*128;
        float s = -1e30f;
        if (m < NN) {
            s = 0.f;
            const float* kr = Kg + (size_t)m * DD;
            #pragma unroll
            for (int d4 = 0; d4 < 64; d4 += 4) {
                float4 k4 = *(const float4*)(kr + d4);
                s += q0s[d4]*k4.x + q0s[d4+1]*k4.y + q0s[d4+2]*k4.z + q0s[d4+3]*k4.w;
            }
            g_cls_logits[(size_t)bh * NN + m] = s;
        }
        lg[i] = s;
        mloc = fmaxf(mloc, s);
    }

    red[tid] = mloc; __syncthreads();
    for (int o = 64; o > 0; o >>= 1) {
        if (tid < o) red[tid] = fmaxf(red[tid], red[tid+o]);
        __syncthreads();
    }
    float mx = red[0];
    __syncthreads();

    float se = 0.f;
    #pragma unroll
    for (int i = 0; i < 5; i++)
        if (lg[i] > -1e29f) se += __expf(lg[i] - mx);
    red[tid] = se; __syncthreads();
    for (int o = 64; o > 0; o >>= 1) {
        if (tid < o) red[tid] += red[tid+o];
        __syncthreads();
    }
    if (tid == 0) { g_cls_max[bh] = mx; g_cls_den[bh] = red[0]; }
}

// Head-mean of CLS logits and CLS attention
__global__ void cls_out_kernel(float* __restrict__ out_cta, float* __restrict__ out_ctl)
{
    int idx = blockIdx.x * blockDim.x + threadIdx.x;
    if (idx >= MTOK) return;
    int b_ = idx / NN;
    int m  = idx - b_ * NN;
    float sl = 0.f, sa = 0.f;
    #pragma unroll
    for (int h = 0; h < HH; h++) {
        int bh = b_ * HH + h;
        float l = g_cls_logits[(size_t)bh * NN + m];
        sl += l;
        sa += __expf(l - g_cls_max[bh]) / g_cls_den[bh];
    }
    out_ctl[idx] = sl * (1.f / 16.f);
    out_cta[idx] = sa * (1.f / 16.f);
}

// ---------------------------------------------------------------------------
extern "C" void kernel_launch(void* const* d_in, const int* in_sizes, int n_in,
                              void* d_out, int out_size)
{
    const float* x      = (const float*)d_in[0];
    const float* w_qkv  = (const float*)d_in[1];
    const float* b_qkv  = (const float*)d_in[2];
    const float* w_proj = (const float*)d_in[3];
    const float* b_proj = (const float*)d_in[4];
    float* out = (float*)d_out;

    // 1) QKV projection + scatter (q scaled) — tf32 tensor cores
    {
        dim3 grid(3*CC/128, (MTOK + 127) / 128);
        mma_gemm_nt<<<grid, 256>>>(x, w_qkv, b_qkv, nullptr, MTOK, 3*CC, 1);
    }

    // 2) Flash attention
    cudaFuncSetAttribute(flash_attn_kernel,
                         cudaFuncAttributeMaxDynamicSharedMemorySize, FLASH_SMEM);
    {
        dim3 grid(10, BB*HH);
        flash_attn_kernel<<<grid, 256, FLASH_SMEM>>>();
    }

    // 3) CLS-row outputs
    cls_logits_kernel<<<BB*HH, 128>>>();
    cls_out_kernel<<<(MTOK + 255) / 256, 256>>>(out + CTA_OFS, out + CTL_OFS);

    // 4) Output projection — tf32 tensor cores
    {
        dim3 grid(CC/128, (MTOK + 127) / 128);
        mma_gemm_nt<<<grid, 256>>>(nullptr, w_proj, b_proj, out, MTOK, CC, 2);
    }
}

// round 6
// speedup vs baseline: 5.1773x; 3.3224x over previous
#include <cuda_runtime.h>
#include <math.h>

// Problem constants
#define BB 16
#define HH 16
#define NN 577
#define DD 64
#define CC 1024
#define MTOK (BB*NN)            // 9232
#define PLANE (BB*HH*NN*DD)     // 9,453,568 floats per q/k/v plane
#define OUT_ELEMS (MTOK*CC)     // 9,453,568
#define CTA_OFS OUT_ELEMS
#define CTL_OFS (OUT_ELEMS + MTOK)
#define QSCALE 0.125f           // 1/sqrt(64)

// Scratch (device globals: allocation-free per harness rules)
__device__ float g_qkv[3u * PLANE];       // [3][B][H][N][D], q pre-scaled
__device__ float g_attn[OUT_ELEMS];       // [B][N][C] attention output
__device__ float g_cls_logits[BB*HH*NN];  // per-head CLS-row logits
__device__ float g_cls_max[BB*HH];
__device__ float g_cls_den[BB*HH];

__device__ __forceinline__ unsigned int f2tf32(float f) {
    unsigned int r;
    asm("cvt.rna.tf32.f32 %0, %1;" : "=r"(r) : "f"(f));
    return r;
}

#define MMA_TF32(d, a, b) \
    asm("mma.sync.aligned.m16n8k8.row.col.f32.tf32.tf32.f32 " \
        "{%0,%1,%2,%3}, {%4,%5,%6,%7}, {%8,%9}, {%0,%1,%2,%3};" \
        : "+f"((d)[0]), "+f"((d)[1]), "+f"((d)[2]), "+f"((d)[3]) \
        : "r"((a)[0]), "r"((a)[1]), "r"((a)[2]), "r"((a)[3]), \
          "r"((b)[0]), "r"((b)[1]))

// ---------------------------------------------------------------------------
// tf32 tensor-core GEMM: C[m,n] = sum_k A[m,k] * W[n,k] (+bias). K = 1024.
// A row-major [M,K], W row-major [N,K] (k-contiguous = mma "col" B operand).
// BM=BN=128, BK=32, 256 threads (8 warps as 4m x 2n, warp tile 32x64).
// mode 1: QKV epilogue -> scatter into g_qkv (q scaled)
// mode 2: A taken from g_attn, plain epilogue into Cout
// ---------------------------------------------------------------------------
#define GSTRIDE 36   // smem row stride in words: bank = row*4+col -> conflict-free

__global__ __launch_bounds__(256) void mma_gemm_nt(
    const float* __restrict__ A, const float* __restrict__ W,
    const float* __restrict__ bias, float* __restrict__ Cout,
    int M, int N, int mode)
{
    __shared__ unsigned int As[128 * GSTRIDE];
    __shared__ unsigned int Ws[128 * GSTRIDE];
    const int K = 1024;

    const float* Abase = (mode == 2) ? g_attn : A;

    const int tid  = threadIdx.x;
    const int lane = tid & 31;
    const int warp = tid >> 5;
    const int wm   = warp & 3;     // warp row (m): 0..3 -> 32 rows each
    const int wn   = warp >> 2;    // warp col (n): 0..1 -> 64 cols each
    const int bm   = blockIdx.y * 128;
    const int bn   = blockIdx.x * 128;

    float acc[2][8][4];
    #pragma unroll
    for (int i = 0; i < 2; i++)
        #pragma unroll
        for (int j = 0; j < 8; j++)
            #pragma unroll
            for (int e = 0; e < 4; e++) acc[i][j][e] = 0.f;

    const int g  = lane >> 2;      // group id 0..7
    const int tg = lane & 3;       // thread in group 0..3

    for (int k0 = 0; k0 < K; k0 += 32) {
        // global loads: 128 rows x 8 float4 = 1024 float4, 4 per thread
        float4 av[4], wv[4];
        #pragma unroll
        for (int i = 0; i < 4; i++) {
            int p   = i * 256 + tid;
            int row = p >> 3;
            int c4  = (p & 7) << 2;
            int ar  = bm + row;
            const float* ap = Abase + (size_t)((ar < M) ? ar : (M - 1)) * K + k0 + c4;
            av[i] = (ar < M) ? *(const float4*)ap : make_float4(0.f, 0.f, 0.f, 0.f);
            wv[i] = *(const float4*)(W + (size_t)(bn + row) * K + k0 + c4);
        }
        __syncthreads();
        #pragma unroll
        for (int i = 0; i < 4; i++) {
            int p   = i * 256 + tid;
            int row = p >> 3;
            int c4  = (p & 7) << 2;
            uint4 at = make_uint4(f2tf32(av[i].x), f2tf32(av[i].y), f2tf32(av[i].z), f2tf32(av[i].w));
            uint4 wt = make_uint4(f2tf32(wv[i].x), f2tf32(wv[i].y), f2tf32(wv[i].z), f2tf32(wv[i].w));
            *(uint4*)(As + row * GSTRIDE + c4) = at;
            *(uint4*)(Ws + row * GSTRIDE + c4) = wt;
        }
        __syncthreads();

        #pragma unroll
        for (int ks = 0; ks < 4; ks++) {
            const int kb = ks << 3;
            unsigned int af[2][4], bf[8][2];
            #pragma unroll
            for (int mt = 0; mt < 2; mt++) {
                int r0 = wm * 32 + mt * 16 + g;
                af[mt][0] = As[r0 * GSTRIDE + kb + tg];
                af[mt][1] = As[(r0 + 8) * GSTRIDE + kb + tg];
                af[mt][2] = As[r0 * GSTRIDE + kb + tg + 4];
                af[mt][3] = As[(r0 + 8) * GSTRIDE + kb + tg + 4];
            }
            #pragma unroll
            for (int nt = 0; nt < 8; nt++) {
                int nr = wn * 64 + nt * 8 + g;
                bf[nt][0] = Ws[nr * GSTRIDE + kb + tg];
                bf[nt][1] = Ws[nr * GSTRIDE + kb + tg + 4];
            }
            #pragma unroll
            for (int mt = 0; mt < 2; mt++)
                #pragma unroll
                for (int nt = 0; nt < 8; nt++)
                    MMA_TF32(acc[mt][nt], af[mt], bf[nt]);
        }
    }

    // Epilogue. c-elem e: row += (e>=2)*8, col = tg*2 + (e&1)
    #pragma unroll
    for (int mt = 0; mt < 2; mt++) {
        #pragma unroll
        for (int eh = 0; eh < 2; eh++) {          // half: rows g / g+8
            int m = bm + wm * 32 + mt * 16 + g + eh * 8;
            if (m >= M) continue;
            if (mode == 1) {
                int b_  = m / NN;
                int tok = m - b_ * NN;
                #pragma unroll
                for (int nt = 0; nt < 8; nt++) {
                    #pragma unroll
                    for (int ec = 0; ec < 2; ec++) {
                        int n = bn + wn * 64 + nt * 8 + tg * 2 + ec;
                        float v = acc[mt][nt][eh * 2 + ec] + bias[n];
                        int which = n >> 10;
                        int rest  = n & 1023;
                        int h = rest >> 6;
                        int d = rest & 63;
                        if (which == 0) v *= QSCALE;
                        g_qkv[(size_t)which * PLANE + (((size_t)(b_ * HH + h) * NN + tok) << 6) + d] = v;
                    }
                }
            } else {
                #pragma unroll
                for (int nt = 0; nt < 8; nt++) {
                    int n = bn + wn * 64 + nt * 8 + tg * 2;
                    float2 v = make_float2(acc[mt][nt][eh * 2 + 0] + bias[n],
                                           acc[mt][nt][eh * 2 + 1] + bias[n + 1]);
                    *(float2*)(Cout + (size_t)m * N + n) = v;
                }
            }
        }
    }
}

// ---------------------------------------------------------------------------
// Tensor-core flash attention (tf32 mma).
// Grid (5 q-tiles of 128, 256 bh), 256 threads = 8 warps x 16 q-rows.
// Key tiles of 64. S = Q K^T via NT mma; softmax on C fragments; P stored
// tf32 in smem (own warp strip); O += P V via mma with B read from row-major
// Vs. O accumulators persist in registers across key tiles.
// ---------------------------------------------------------------------------
#define FA_SROW 68
#define FA_BQ   128
#define FA_SMEM ((FA_BQ*FA_SROW + 64*FA_SROW + 64*FA_SROW + FA_BQ*FA_SROW) * 4)

__global__ __launch_bounds__(256) void flash_mma_kernel()
{
    extern __shared__ unsigned int smu[];
    unsigned int* Qs = smu;                      // [128][68] tf32
    unsigned int* Ks = Qs + FA_BQ * FA_SROW;     // [64][68]  tf32
    unsigned int* Vs = Ks + 64 * FA_SROW;        // [64][68]  tf32
    unsigned int* Ps = Vs + 64 * FA_SROW;        // [128][68] tf32

    const int tid  = threadIdx.x;
    const int lane = tid & 31;
    const int warp = tid >> 5;
    const int g    = lane >> 2;
    const int tg   = lane & 3;
    const int qt   = blockIdx.x;          // 0..4
    const int bh   = blockIdx.y;          // 0..255
    const int q0g  = qt * FA_BQ;
    const int wr   = warp * 16;           // warp's q-row base in tile

    const float* Qg = g_qkv + (size_t)bh * NN * DD;
    const float* Kg = g_qkv + (size_t)PLANE + (size_t)bh * NN * DD;
    const float* Vg = g_qkv + 2u * (size_t)PLANE + (size_t)bh * NN * DD;

    // Load Q tile (tf32). 128 rows x 16 float4 = 2048, 8 per thread.
    #pragma unroll
    for (int i = 0; i < 8; i++) {
        int p   = i * 256 + tid;
        int row = p >> 4;
        int c4  = (p & 15) << 2;
        int tok = q0g + row; if (tok > NN - 1) tok = NN - 1;   // clamp (rows >= NN unused)
        float4 v = *(const float4*)(Qg + (size_t)tok * DD + c4);
        *(uint4*)(Qs + row * FA_SROW + c4) =
            make_uint4(f2tf32(v.x), f2tf32(v.y), f2tf32(v.z), f2tf32(v.w));
    }

    float oacc[8][4];
    #pragma unroll
    for (int nt = 0; nt < 8; nt++)
        #pragma unroll
        for (int e = 0; e < 4; e++) oacc[nt][e] = 0.f;
    float m_i[2] = { -1e30f, -1e30f };
    float l_i[2] = { 0.f, 0.f };

    for (int kt = 0; kt < 10; kt++) {
        const int k0g = kt * 64;
        __syncthreads();   // prior-iteration Vs/Ks reads complete (also covers Q store)

        // Load K/V tiles (tf32). 64 rows x 16 float4 each, 4+4 per thread.
        #pragma unroll
        for (int i = 0; i < 4; i++) {
            int p   = i * 256 + tid;
            int row = p >> 4;
            int c4  = (p & 15) << 2;
            int tok = k0g + row; if (tok > NN - 1) tok = NN - 1;  // clamp (masked later)
            float4 kv = *(const float4*)(Kg + (size_t)tok * DD + c4);
            float4 vv = *(const float4*)(Vg + (size_t)tok * DD + c4);
            *(uint4*)(Ks + row * FA_SROW + c4) =
                make_uint4(f2tf32(kv.x), f2tf32(kv.y), f2tf32(kv.z), f2tf32(kv.w));
            *(uint4*)(Vs + row * FA_SROW + c4) =
                make_uint4(f2tf32(vv.x), f2tf32(vv.y), f2tf32(vv.z), f2tf32(vv.w));
        }
        __syncthreads();

        // ---- S = Q K^T : 16 q-rows x 64 keys per warp ----
        float sacc[8][4];
        #pragma unroll
        for (int nt = 0; nt < 8; nt++)
            #pragma unroll
            for (int e = 0; e < 4; e++) sacc[nt][e] = 0.f;

        #pragma unroll
        for (int ks = 0; ks < 8; ks++) {
            const int kb = ks << 3;
            unsigned int af[4], bf[8][2];
            af[0] = Qs[(wr + g) * FA_SROW + kb + tg];
            af[1] = Qs[(wr + g + 8) * FA_SROW + kb + tg];
            af[2] = Qs[(wr + g) * FA_SROW + kb + tg + 4];
            af[3] = Qs[(wr + g + 8) * FA_SROW + kb + tg + 4];
            #pragma unroll
            for (int nt = 0; nt < 8; nt++) {
                bf[nt][0] = Ks[(nt * 8 + g) * FA_SROW + kb + tg];
                bf[nt][1] = Ks[(nt * 8 + g) * FA_SROW + kb + tg + 4];
            }
            #pragma unroll
            for (int nt = 0; nt < 8; nt++)
                MMA_TF32(sacc[nt], af, bf[nt]);
        }

        // ---- online softmax on fragments (rows wr+g and wr+g+8) ----
        #pragma unroll
        for (int eh = 0; eh < 2; eh++) {
            float mloc = -1e30f;
            #pragma unroll
            for (int nt = 0; nt < 8; nt++) {
                #pragma unroll
                for (int ec = 0; ec < 2; ec++) {
                    int key = k0g + nt * 8 + tg * 2 + ec;
                    if (key >= NN) sacc[nt][eh * 2 + ec] = -1e30f;
                    mloc = fmaxf(mloc, sacc[nt][eh * 2 + ec]);
                }
            }
            mloc = fmaxf(mloc, __shfl_xor_sync(0xffffffffu, mloc, 1));
            mloc = fmaxf(mloc, __shfl_xor_sync(0xffffffffu, mloc, 2));
            float m_new = fmaxf(m_i[eh], mloc);
            float alpha = __expf(m_i[eh] - m_new);

            float psum = 0.f;
            int prow = (wr + g + eh * 8) * FA_SROW;
            #pragma unroll
            for (int nt = 0; nt < 8; nt++) {
                float p0 = __expf(sacc[nt][eh * 2 + 0] - m_new);
                float p1 = __expf(sacc[nt][eh * 2 + 1] - m_new);
                psum += p0 + p1;
                *(uint2*)(Ps + prow + nt * 8 + tg * 2) = make_uint2(f2tf32(p0), f2tf32(p1));
            }
            psum += __shfl_xor_sync(0xffffffffu, psum, 1);
            psum += __shfl_xor_sync(0xffffffffu, psum, 2);
            l_i[eh] = l_i[eh] * alpha + psum;
            m_i[eh] = m_new;
            #pragma unroll
            for (int nt = 0; nt < 8; nt++) {
                oacc[nt][eh * 2 + 0] *= alpha;
                oacc[nt][eh * 2 + 1] *= alpha;
            }
        }
        __syncwarp();   // Ps strip visible within warp

        // ---- O += P V : A = P (own strip), B = Vs rows j, cols d ----
        #pragma unroll
        for (int ks = 0; ks < 8; ks++) {
            const int kb = ks << 3;     // key j block
            unsigned int af[4], bf[8][2];
            af[0] = Ps[(wr + g) * FA_SROW + kb + tg];
            af[1] = Ps[(wr + g + 8) * FA_SROW + kb + tg];
            af[2] = Ps[(wr + g) * FA_SROW + kb + tg + 4];
            af[3] = Ps[(wr + g + 8) * FA_SROW + kb + tg + 4];
            #pragma unroll
            for (int nt = 0; nt < 8; nt++) {
                bf[nt][0] = Vs[(kb + tg) * FA_SROW + nt * 8 + g];
                bf[nt][1] = Vs[(kb + tg + 4) * FA_SROW + nt * 8 + g];
            }
            #pragma unroll
            for (int nt = 0; nt < 8; nt++)
                MMA_TF32(oacc[nt], af, bf[nt]);
        }
        __syncwarp();   // Ps reads done before next-iter overwrite
    }

    // ---- write O / l ----
    const int b_ = bh >> 4, h = bh & 15;
    #pragma unroll
    for (int eh = 0; eh < 2; eh++) {
        int tok = q0g + wr + g + eh * 8;
        if (tok >= NN) continue;
        float inv = 1.f / l_i[eh];
        float* o = g_attn + ((size_t)b_ * NN + tok) * CC + h * DD;
        #pragma unroll
        for (int nt = 0; nt < 8; nt++) {
            float2 v = make_float2(oacc[nt][eh * 2 + 0] * inv,
                                   oacc[nt][eh * 2 + 1] * inv);
            *(float2*)(o + nt * 8 + tg * 2) = v;
        }
    }
}

// ---------------------------------------------------------------------------
// CLS-row logits per (b,h): logits[m] = q0 . k[m]; also max & softmax denom
// ---------------------------------------------------------------------------
__global__ __launch_bounds__(128) void cls_logits_kernel()
{
    __shared__ float q0s[64];
    __shared__ float red[128];
    const int bh  = blockIdx.x;
    const int tid = threadIdx.x;
    const float* Qg = g_qkv + (size_t)bh * NN * DD;            // q already scaled
    const float* Kg = g_qkv + (size_t)PLANE + (size_t)bh * NN * DD;

    if (tid < 64) q0s[tid] = Qg[tid];
    __syncthreads();

    float lg[5];
    float mloc = -1e30f;
    #pragma unroll
    for (int i = 0; i < 5; i++) {
        int m = tid + i*128;
        float s = -1e30f;
        if (m < NN) {
            s = 0.f;
            const float* kr = Kg + (size_t)m * DD;
            #pragma unroll
            for (int d4 = 0; d4 < 64; d4 += 4) {
                float4 k4 = *(const float4*)(kr + d4);
                s += q0s[d4]*k4.x + q0s[d4+1]*k4.y + q0s[d4+2]*k4.z + q0s[d4+3]*k4.w;
            }
            g_cls_logits[(size_t)bh * NN + m] = s;
        }
        lg[i] = s;
        mloc = fmaxf(mloc, s);
    }

    red[tid] = mloc; __syncthreads();
    for (int o = 64; o > 0; o >>= 1) {
        if (tid < o) red[tid] = fmaxf(red[tid], red[tid+o]);
        __syncthreads();
    }
    float mx = red[0];
    __syncthreads();

    float se = 0.f;
    #pragma unroll
    for (int i = 0; i < 5; i++)
        if (lg[i] > -1e29f) se += __expf(lg[i] - mx);
    red[tid] = se; __syncthreads();
    for (int o = 64; o > 0; o >>= 1) {
        if (tid < o) red[tid] += red[tid+o];
        __syncthreads();
    }
    if (tid == 0) { g_cls_max[bh] = mx; g_cls_den[bh] = red[0]; }
}

// Head-mean of CLS logits and CLS attention
__global__ void cls_out_kernel(float* __restrict__ out_cta, float* __restrict__ out_ctl)
{
    int idx = blockIdx.x * blockDim.x + threadIdx.x;
    if (idx >= MTOK) return;
    int b_ = idx / NN;
    int m  = idx - b_ * NN;
    float sl = 0.f, sa = 0.f;
    #pragma unroll
    for (int h = 0; h < HH; h++) {
        int bh = b_ * HH + h;
        float l = g_cls_logits[(size_t)bh * NN + m];
        sl += l;
        sa += __expf(l - g_cls_max[bh]) / g_cls_den[bh];
    }
    out_ctl[idx] = sl * (1.f / 16.f);
    out_cta[idx] = sa * (1.f / 16.f);
}

// ---------------------------------------------------------------------------
extern "C" void kernel_launch(void* const* d_in, const int* in_sizes, int n_in,
                              void* d_out, int out_size)
{
    const float* x      = (const float*)d_in[0];
    const float* w_qkv  = (const float*)d_in[1];
    const float* b_qkv  = (const float*)d_in[2];
    const float* w_proj = (const float*)d_in[3];
    const float* b_proj = (const float*)d_in[4];
    float* out = (float*)d_out;

    // 1) QKV projection + scatter (q scaled) — tf32 tensor cores
    {
        dim3 grid(3*CC/128, (MTOK + 127) / 128);
        mma_gemm_nt<<<grid, 256>>>(x, w_qkv, b_qkv, nullptr, MTOK, 3*CC, 1);
    }

    // 2) Flash attention — tf32 tensor cores
    cudaFuncSetAttribute(flash_mma_kernel,
                         cudaFuncAttributeMaxDynamicSharedMemorySize, FA_SMEM);
    {
        dim3 grid((NN + FA_BQ - 1) / FA_BQ, BB*HH);   // (5, 256)
        flash_mma_kernel<<<grid, 256, FA_SMEM>>>();
    }

    // 3) CLS-row outputs (full fp32)
    cls_logits_kernel<<<BB*HH, 128>>>();
    cls_out_kernel<<<(MTOK + 255) / 256, 256>>>(out + CTA_OFS, out + CTL_OFS);

    // 4) Output projection — tf32 tensor cores
    {
        dim3 grid(CC/128, (MTOK + 127) / 128);
        mma_gemm_nt<<<grid, 256>>>(nullptr, w_proj, b_proj, out, MTOK, CC, 2);
    }
}